// round 4
// baseline (speedup 1.0000x reference)
#include <cuda_runtime.h>
#include <cuda_bf16.h>
#include <cstdint>

// Problem shapes
#define NCLS 5
#define MIMG 512
#define PP   196
#define DD   384
#define NROWS_Q (MIMG * PP)
#define NROWS_S (NCLS * PP)

#define ROWB 768            // bytes per feature row (384 bf16)
#define NCH  48             // 16B chunks per row
#define AP   208            // padded A rows (13 x 16)
#define BCOLS 32            // B chunk columns (support patches per chunk)
#define NCHUNKS 7           // ceil(196/32)
#define KSTEPS 24           // 384 / 16

#define ASIZE (AP * ROWB)           // 159744
#define BSIZE (BCOLS * ROWB)        // 24576
#define SM_B0 ASIZE
#define SM_B1 (ASIZE + BSIZE)
#define SM_RM (ASIZE + 2 * BSIZE)   // 208896
#define SMEM_BYTES (SM_RM + AP * 4) // 209728

// Normalized bf16 copies (device-global scratch: allowed)
__device__ __nv_bfloat16 g_QN[(size_t)NROWS_Q * DD];
__device__ __nv_bfloat16 g_SN[(size_t)NROWS_S * DD];

// ---------------- helpers ----------------
static __device__ __forceinline__ uint32_t smem_u32(const void* p) {
    uint32_t a;
    asm("{ .reg .u64 t; cvta.to.shared.u64 t, %1; cvt.u32.u64 %0, t; }" : "=r"(a) : "l"(p));
    return a;
}

static __device__ __forceinline__ void cp16(uint32_t dst, const void* src, int ok) {
    asm volatile("cp.async.cg.shared.global [%0], [%1], 16, %2;"
                 :: "r"(dst), "l"(src), "r"(ok ? 16 : 0) : "memory");
}
#define CP_COMMIT() asm volatile("cp.async.commit_group;" ::: "memory")
#define CP_WAIT0()  asm volatile("cp.async.wait_group 0;" ::: "memory")

static __device__ __forceinline__ void ldsm4(uint32_t& d0, uint32_t& d1,
                                             uint32_t& d2, uint32_t& d3, uint32_t addr) {
    asm volatile("ldmatrix.sync.aligned.m8n8.x4.shared.b16 {%0,%1,%2,%3}, [%4];"
                 : "=r"(d0), "=r"(d1), "=r"(d2), "=r"(d3) : "r"(addr));
}

static __device__ __forceinline__ void mma16816(float* c,
        uint32_t a0, uint32_t a1, uint32_t a2, uint32_t a3,
        uint32_t b0, uint32_t b1) {
    asm volatile(
        "mma.sync.aligned.m16n8k16.row.col.f32.bf16.bf16.f32 "
        "{%0,%1,%2,%3}, {%4,%5,%6,%7}, {%8,%9}, {%0,%1,%2,%3};"
        : "+f"(c[0]), "+f"(c[1]), "+f"(c[2]), "+f"(c[3])
        : "r"(a0), "r"(a1), "r"(a2), "r"(a3), "r"(b0), "r"(b1));
}

// ---------------- Kernel 1: L2-normalize rows -> bf16 ----------------
__global__ __launch_bounds__(128) void norm_kernel(
    const float* __restrict__ support, const float* __restrict__ query)
{
    int row  = blockIdx.x * 4 + (threadIdx.x >> 5);
    int lane = threadIdx.x & 31;
    const float* src;
    __nv_bfloat16* dst;
    if (row < NROWS_Q) {
        src = query + (size_t)row * DD;
        dst = g_QN  + (size_t)row * DD;
    } else {
        int r = row - NROWS_Q;
        if (r >= NROWS_S) return;
        src = support + (size_t)r * DD;
        dst = g_SN    + (size_t)r * DD;
    }
    const float4* s4 = (const float4*)src;
    float4 v[3];
    float ss = 0.f;
#pragma unroll
    for (int j = 0; j < 3; j++) {
        v[j] = s4[lane * 3 + j];
        ss += v[j].x * v[j].x + v[j].y * v[j].y + v[j].z * v[j].z + v[j].w * v[j].w;
    }
#pragma unroll
    for (int o = 16; o; o >>= 1) ss += __shfl_xor_sync(0xffffffffu, ss, o);
    float inv = 1.0f / fmaxf(sqrtf(ss), 1e-12f);

    uint2* d2 = (uint2*)dst;
#pragma unroll
    for (int j = 0; j < 3; j++) {
        __nv_bfloat162 h0 = __floats2bfloat162_rn(v[j].x * inv, v[j].y * inv);
        __nv_bfloat162 h1 = __floats2bfloat162_rn(v[j].z * inv, v[j].w * inv);
        uint2 u;
        u.x = *reinterpret_cast<uint32_t*>(&h0);
        u.y = *reinterpret_cast<uint32_t*>(&h1);
        d2[lane * 3 + j] = u;
    }
}

// ---------------- chunk GEMM + rowmax (templated on #m-tiles) ----------------
// Warp tile: MT*16 rows x 32 cols, mma.m16n8k16. Smem rows swizzled:
// 16B-chunk' = chunk ^ (row & 7); since all row bases are multiples of 8,
// row & 7 == (lane & 7) for every ldmatrix address -> conflict-free.
template <int MT>
static __device__ __forceinline__ void gemm_chunk(
    uint32_t sb, uint32_t Bb, int wbase, int lane, int ncbase, float* rmax)
{
    const int lm = lane >> 3;
    const int lr = lane & 7;
    const int arow = ((lm & 1) << 3) + lr;   // A: matrices (r0-7,k0-7),(r8-15,k0-7),(r0-7,k8-15),(r8-15,k8-15)
    const int ahalf = lm >> 1;
    const int brow = ((lm >> 1) << 3) + lr;  // B: (n0-7,k0-7),(n0-7,k8-15),(n8-15,k0-7),(n8-15,k8-15)
    const int bhalf = lm & 1;

    uint32_t a_base0 = sb + (uint32_t)(wbase + arow) * ROWB;
    uint32_t a_base1 = a_base0 + 16 * ROWB;
    uint32_t b_base0 = Bb + (uint32_t)brow * ROWB;
    uint32_t b_base1 = b_base0 + 16 * ROWB;

    float acc[MT][4][4];
#pragma unroll
    for (int mt = 0; mt < MT; mt++)
#pragma unroll
        for (int nt = 0; nt < 4; nt++)
#pragma unroll
            for (int j = 0; j < 4; j++) acc[mt][nt][j] = 0.f;

#pragma unroll
    for (int k = 0; k < KSTEPS; k++) {
        uint32_t aoff = (uint32_t)((((k << 1) + ahalf) ^ lr) << 4);
        uint32_t boff = (uint32_t)((((k << 1) + bhalf) ^ lr) << 4);
        uint32_t b0, b1, b2, b3, b4, b5, b6, b7;
        ldsm4(b0, b1, b2, b3, b_base0 + boff);
        ldsm4(b4, b5, b6, b7, b_base1 + boff);
        uint32_t a0, a1, a2, a3;
        ldsm4(a0, a1, a2, a3, a_base0 + aoff);
        mma16816(acc[0][0], a0, a1, a2, a3, b0, b1);
        mma16816(acc[0][1], a0, a1, a2, a3, b2, b3);
        mma16816(acc[0][2], a0, a1, a2, a3, b4, b5);
        mma16816(acc[0][3], a0, a1, a2, a3, b6, b7);
        if (MT > 1) {
            uint32_t e0, e1, e2, e3;
            ldsm4(e0, e1, e2, e3, a_base1 + aoff);
            mma16816(acc[1][0], e0, e1, e2, e3, b0, b1);
            mma16816(acc[1][1], e0, e1, e2, e3, b2, b3);
            mma16816(acc[1][2], e0, e1, e2, e3, b4, b5);
            mma16816(acc[1][3], e0, e1, e2, e3, b6, b7);
        }
    }

    // fold into running row-max; mask padded support columns (col >= 196)
#pragma unroll
    for (int mt = 0; mt < MT; mt++)
#pragma unroll
        for (int nt = 0; nt < 4; nt++)
#pragma unroll
            for (int j = 0; j < 4; j++) {
                int col = ncbase + nt * 8 + ((lane & 3) << 1) + (j & 1);
                if (col < PP)
                    rmax[mt * 2 + (j >> 1)] = fmaxf(rmax[mt * 2 + (j >> 1)], acc[mt][nt][j]);
            }
}

// ---------------- Kernel 2: per-(m,c) GEMM + rowmax + top-6 ----------------
__global__ __launch_bounds__(256, 1) void protonet_kernel(
    const float* __restrict__ scale_cls, const float* __restrict__ bias,
    float* __restrict__ out)
{
    extern __shared__ char smem[];
    const uint32_t sb = smem_u32(smem);
    const int tid = threadIdx.x, wid = tid >> 5, lane = tid & 31;
    const int c = blockIdx.x, m = blockIdx.y;

    const char* qg = (const char*)(g_QN + (size_t)m * PP * DD);
    const char* sg = (const char*)(g_SN + (size_t)c * PP * DD);

    // prologue: A (full, zero-pad rows >=196) + B chunk 0
    for (int i = tid; i < AP * NCH; i += 256) {
        int r = i / NCH, ch = i % NCH;
        uint32_t dst = sb + (uint32_t)r * ROWB + (uint32_t)((ch ^ (r & 7)) << 4);
        int ok = r < PP;
        cp16(dst, qg + (ok ? ((size_t)r * ROWB + (ch << 4)) : 0), ok);
    }
    for (int i = tid; i < BCOLS * NCH; i += 256) {
        int r = i / NCH, ch = i % NCH;
        uint32_t dst = sb + SM_B0 + (uint32_t)r * ROWB + (uint32_t)((ch ^ (r & 7)) << 4);
        int ok = r < PP;   // chunk 0: q = r
        cp16(dst, sg + (ok ? ((size_t)r * ROWB + (ch << 4)) : 0), ok);
    }
    CP_COMMIT();

    const float NEG = __int_as_float(0xff800000);
    float rmax[4] = {NEG, NEG, NEG, NEG};
    const int mtcnt = (wid < 6) ? 2 : ((wid == 6) ? 1 : 0);
    const int wbase = wid * 32;

    for (int nc = 0; nc < NCHUNKS; nc++) {
        CP_WAIT0();
        __syncthreads();
        if (nc + 1 < NCHUNKS) {
            int nb = nc + 1;
            uint32_t bb = sb + ((nb & 1) ? SM_B1 : SM_B0);
            for (int i = tid; i < BCOLS * NCH; i += 256) {
                int r = i / NCH, ch = i % NCH;
                int q = nb * BCOLS + r;
                uint32_t dst = bb + (uint32_t)r * ROWB + (uint32_t)((ch ^ (r & 7)) << 4);
                int ok = q < PP;
                cp16(dst, sg + (ok ? ((size_t)q * ROWB + (ch << 4)) : 0), ok);
            }
            CP_COMMIT();
        }
        uint32_t Bb = sb + ((nc & 1) ? SM_B1 : SM_B0);
        if (mtcnt == 2)      gemm_chunk<2>(sb, Bb, wbase, lane, nc * BCOLS, rmax);
        else if (mtcnt == 1) gemm_chunk<1>(sb, Bb, wbase, lane, nc * BCOLS, rmax);
    }

    // reduce row-max across the 4 lanes of each quad (they hold disjoint cols)
#pragma unroll
    for (int o = 1; o <= 2; o <<= 1)
#pragma unroll
        for (int i = 0; i < 4; i++)
            rmax[i] = fmaxf(rmax[i], __shfl_xor_sync(0xffffffffu, rmax[i], o));

    float* rm = (float*)(smem + SM_RM);
    if ((lane & 3) == 0 && mtcnt) {
#pragma unroll
        for (int mt = 0; mt < 2; mt++) {
            if (mt >= mtcnt) break;
#pragma unroll
            for (int h = 0; h < 2; h++) {
                int row = wbase + mt * 16 + h * 8 + (lane >> 2);
                if (row < PP) rm[row] = rmax[mt * 2 + h];
            }
        }
    }
    __syncthreads();

    // top-6 over 196 row-max values (warp 0)
    if (wid == 0) {
        float v[7];
#pragma unroll
        for (int k = 0; k < 7; k++) {
            int idx = lane + 32 * k;
            v[k] = (idx < PP) ? rm[idx] : NEG;
        }
        float sum = 0.f;
#pragma unroll
        for (int it = 0; it < 6; it++) {
            float best = v[0]; int bslot = 0;
#pragma unroll
            for (int k = 1; k < 7; k++)
                if (v[k] > best) { best = v[k]; bslot = k; }
            int bid = lane;
#pragma unroll
            for (int o = 16; o; o >>= 1) {
                float ov = __shfl_xor_sync(0xffffffffu, best, o);
                int  oid = __shfl_xor_sync(0xffffffffu, bid, o);
                int  osl = __shfl_xor_sync(0xffffffffu, bslot, o);
                if (ov > best || (ov == best && oid < bid)) {
                    best = ov; bid = oid; bslot = osl;
                }
            }
            sum += best;
            if (lane == bid) v[bslot] = NEG;
        }
        if (lane == 0)
            out[m * NCLS + c] = scale_cls[0] * (sum + bias[0]);
    }
}

// ---------------- launch ----------------
extern "C" void kernel_launch(void* const* d_in, const int* in_sizes, int n_in,
                              void* d_out, int out_size)
{
    (void)in_sizes; (void)n_in; (void)out_size;
    const float* support   = (const float*)d_in[0];
    const float* query     = (const float*)d_in[1];
    const float* scale_cls = (const float*)d_in[2];
    const float* bias      = (const float*)d_in[3];
    float* out = (float*)d_out;

    int nrows = NROWS_Q + NROWS_S;
    norm_kernel<<<(nrows + 3) / 4, 128>>>(support, query);

    static int smem_set = 0;
    if (!smem_set) {
        cudaFuncSetAttribute(protonet_kernel,
                             cudaFuncAttributeMaxDynamicSharedMemorySize, SMEM_BYTES);
        smem_set = 1;
    }
    // grid.x = class (Sn tiny, always L2-resident); grid.y = m so one wave
    // shares Qn rows across the 5 classes via L2.
    protonet_kernel<<<dim3(NCLS, MIMG), 256, SMEM_BYTES>>>(scale_cls, bias, out);
}

// round 7
// speedup vs baseline: 1.0085x; 1.0085x over previous
#include <cuda_runtime.h>
#include <cuda_bf16.h>
#include <cstdint>

// Problem shapes
#define NCLS 5
#define MIMG 512
#define PP   196
#define DD   384
#define NROWS_Q (MIMG * PP)
#define NROWS_S (NCLS * PP)

#define ROWB 768            // bytes per feature row (384 bf16)
#define NCHA 48             // 16B chunks per A row
#define AP   208            // physical padded A rows
#define BN   112            // B chunk columns (n per chunk)
#define BKB  256            // bytes per B row per k-chunk (128 k * 2B)
#define NNC  2              // n chunks (224 padded)
#define NKC  3              // k chunks of 128
#define NIT  (NNC * NKC)    // 6 pipeline iterations

#define ASIZE (AP * ROWB)             // 159744
#define BSIZE (BN * BKB)              // 28672
#define SM_B0 ASIZE
#define SM_B1 (ASIZE + BSIZE)
#define SM_RM (ASIZE + 2 * BSIZE)     // 217088
#define SMEM_BYTES (SM_RM + AP * 4)   // 217920

// Normalized bf16 copies (device-global scratch: allowed)
__device__ __nv_bfloat16 g_QN[(size_t)NROWS_Q * DD];
__device__ __nv_bfloat16 g_SN[(size_t)NROWS_S * DD];

// ---------------- helpers ----------------
static __device__ __forceinline__ uint32_t smem_u32(const void* p) {
    uint32_t a;
    asm("{ .reg .u64 t; cvta.to.shared.u64 t, %1; cvt.u32.u64 %0, t; }" : "=r"(a) : "l"(p));
    return a;
}

static __device__ __forceinline__ void cp16(uint32_t dst, const void* src) {
    asm volatile("cp.async.cg.shared.global [%0], [%1], 16;"
                 :: "r"(dst), "l"(src) : "memory");
}
#define CP_COMMIT() asm volatile("cp.async.commit_group;" ::: "memory")
#define CP_WAIT0()  asm volatile("cp.async.wait_group 0;" ::: "memory")
#define CP_WAIT1()  asm volatile("cp.async.wait_group 1;" ::: "memory")

static __device__ __forceinline__ void ldsm4(uint32_t& d0, uint32_t& d1,
                                             uint32_t& d2, uint32_t& d3, uint32_t addr) {
    asm volatile("ldmatrix.sync.aligned.m8n8.x4.shared.b16 {%0,%1,%2,%3}, [%4];"
                 : "=r"(d0), "=r"(d1), "=r"(d2), "=r"(d3) : "r"(addr));
}
static __device__ __forceinline__ void ldsm2(uint32_t& d0, uint32_t& d1, uint32_t addr) {
    asm volatile("ldmatrix.sync.aligned.m8n8.x2.shared.b16 {%0,%1}, [%2];"
                 : "=r"(d0), "=r"(d1) : "r"(addr));
}

static __device__ __forceinline__ void mma16816(float* c,
        uint32_t a0, uint32_t a1, uint32_t a2, uint32_t a3,
        uint32_t b0, uint32_t b1) {
    asm volatile(
        "mma.sync.aligned.m16n8k16.row.col.f32.bf16.bf16.f32 "
        "{%0,%1,%2,%3}, {%4,%5,%6,%7}, {%8,%9}, {%0,%1,%2,%3};"
        : "+f"(c[0]), "+f"(c[1]), "+f"(c[2]), "+f"(c[3])
        : "r"(a0), "r"(a1), "r"(a2), "r"(a3), "r"(b0), "r"(b1));
}

// ---------------- Kernel 1: L2-normalize rows -> bf16 ----------------
__global__ __launch_bounds__(128) void norm_kernel(
    const float* __restrict__ support, const float* __restrict__ query)
{
    int row  = blockIdx.x * 4 + (threadIdx.x >> 5);
    int lane = threadIdx.x & 31;
    const float* src;
    __nv_bfloat16* dst;
    if (row < NROWS_Q) {
        src = query + (size_t)row * DD;
        dst = g_QN  + (size_t)row * DD;
    } else {
        int r = row - NROWS_Q;
        if (r >= NROWS_S) return;
        src = support + (size_t)r * DD;
        dst = g_SN    + (size_t)r * DD;
    }
    const float4* s4 = (const float4*)src;
    float4 v[3];
    float ss = 0.f;
#pragma unroll
    for (int j = 0; j < 3; j++) {
        v[j] = s4[lane * 3 + j];
        ss += v[j].x * v[j].x + v[j].y * v[j].y + v[j].z * v[j].z + v[j].w * v[j].w;
    }
#pragma unroll
    for (int o = 16; o; o >>= 1) ss += __shfl_xor_sync(0xffffffffu, ss, o);
    float inv = 1.0f / fmaxf(sqrtf(ss), 1e-12f);

    uint2* d2 = (uint2*)dst;
#pragma unroll
    for (int j = 0; j < 3; j++) {
        __nv_bfloat162 h0 = __floats2bfloat162_rn(v[j].x * inv, v[j].y * inv);
        __nv_bfloat162 h1 = __floats2bfloat162_rn(v[j].z * inv, v[j].w * inv);
        uint2 u;
        u.x = *reinterpret_cast<uint32_t*>(&h0);
        u.y = *reinterpret_cast<uint32_t*>(&h1);
        d2[lane * 3 + j] = u;
    }
}

// ---------------- Kernel 2: per-(m,c) GEMM + rowmax + top-6 ----------------
// 8 warps = 4 M-slots (64 rows, a=4 x m16) x 2 N-slots (56 cols, b=7 x n8).
// M padded to 256 logically; physical A smem has 208 rows, phantom tiles
// alias rows 192-207 (outputs discarded via row<196 guard).
// N padded to 224 = 2 chunks of 112. K = 3 chunks of 128, B double-buffered.
__global__ __launch_bounds__(256, 1) void protonet_kernel(
    const float* __restrict__ scale_cls, const float* __restrict__ bias,
    float* __restrict__ out)
{
    extern __shared__ char smem[];
    const uint32_t sb = smem_u32(smem);
    const int tid = threadIdx.x, wid = tid >> 5, lane = tid & 31;
    const int c = blockIdx.x, m = blockIdx.y;
    const int mslot = wid >> 1;          // 0..3
    const int nslot = wid & 1;           // 0..1
    const int nbase = nslot * 56;

    const char* qg = (const char*)(g_QN + (size_t)m * PP * DD);
    const char* sg = (const char*)(g_SN + (size_t)c * PP * DD);

    // ---- prologue: A (full K, 208 rows) + B(it0) as group0, B(it1) as group1
    for (int i = tid; i < AP * NCHA; i += 256) {
        int r = i / NCHA, ch = i % NCHA;
        int rc = r < PP ? r : PP - 1;
        cp16(sb + (uint32_t)r * ROWB + (uint32_t)((ch ^ (r & 7)) << 4),
             qg + (size_t)rc * ROWB + (ch << 4));
    }
    {   // B it0: nc=0, kc=0 -> buf0
        for (int i = tid; i < BN * 16; i += 256) {
            int r = i >> 4, ch = i & 15;
            int q = r < PP ? r : PP - 1;
            cp16(sb + SM_B0 + (uint32_t)r * BKB + (uint32_t)((ch ^ (r & 7)) << 4),
                 sg + (size_t)q * ROWB + (ch << 4));
        }
    }
    CP_COMMIT();
    {   // B it1: nc=0, kc=1 -> buf1
        for (int i = tid; i < BN * 16; i += 256) {
            int r = i >> 4, ch = i & 15;
            int q = r < PP ? r : PP - 1;
            cp16(sb + SM_B1 + (uint32_t)r * BKB + (uint32_t)((ch ^ (r & 7)) << 4),
                 sg + (size_t)q * ROWB + 256 + (ch << 4));
        }
    }
    CP_COMMIT();

    // ---- fragment addressing ----
    const int lm = lane >> 3, lr = lane & 7;
    const int arow  = ((lm & 1) << 3) + lr;   // A ldsm: (r0-7,k0)(r8-15,k0)(r0-7,k1)(r8-15,k1)
    const int ahalf = lm >> 1;
    const int brow  = ((lm >> 1) << 3) + lr;  // B ldsm x4: (n0-7,k0)(n0-7,k1)(n8-15,k0)(n8-15,k1)
    const int bhalf = lm & 1;
    const int b6row = lane & 7;               // B ldsm x2 (lanes 0-15 meaningful)
    const int b6half = (lane >> 3) & 1;

    uint32_t a_base[4];
#pragma unroll
    for (int mt = 0; mt < 4; mt++) {
        int rb = mslot * 64 + mt * 16;
        if (rb > 192) rb = 192;               // phantom tiles alias rows 192-207
        a_base[mt] = sb + (uint32_t)(rb + arow) * ROWB;
    }

    const float NEG = __int_as_float(0xff800000);
    float rmax[8];
#pragma unroll
    for (int i = 0; i < 8; i++) rmax[i] = NEG;

    float acc[4][7][4];

#pragma unroll 1
    for (int it = 0; it < NIT; it++) {
        const int nc = it / NKC, kc = it - nc * NKC;
        if (kc == 0) {
#pragma unroll
            for (int mt = 0; mt < 4; mt++)
#pragma unroll
                for (int nt = 0; nt < 7; nt++)
#pragma unroll
                    for (int j = 0; j < 4; j++) acc[mt][nt][j] = 0.f;
        }

        if (it < NIT - 1) CP_WAIT1(); else CP_WAIT0();
        __syncthreads();

        if (it + 1 < NIT) {   // prefetch B for it+1 into the other buffer
            int nit = it + 1;
            int nnc = nit / NKC, nkc = nit - nnc * NKC;
            uint32_t bb = sb + ((nit & 1) ? SM_B1 : SM_B0);
            for (int i = tid; i < BN * 16; i += 256) {
                int r = i >> 4, ch = i & 15;
                int q = nnc * BN + r;
                if (q > PP - 1) q = PP - 1;
                cp16(bb + (uint32_t)r * BKB + (uint32_t)((ch ^ (r & 7)) << 4),
                     sg + (size_t)q * ROWB + nkc * 256 + (ch << 4));
            }
            CP_COMMIT();
        }

        const uint32_t bbuf = sb + ((it & 1) ? SM_B1 : SM_B0);
        uint32_t b_base[3], b_base6;
#pragma unroll
        for (int p = 0; p < 3; p++)
            b_base[p] = bbuf + (uint32_t)(nbase + p * 16 + brow) * BKB;
        b_base6 = bbuf + (uint32_t)(nbase + 48 + b6row) * BKB;

#pragma unroll
        for (int kk = 0; kk < 8; kk++) {
            const int ks = kc * 8 + kk;
            const uint32_t aoff = (uint32_t)((((ks << 1) + ahalf) ^ lr) << 4);
            const uint32_t boff = (uint32_t)((((kk << 1) + bhalf) ^ lr) << 4);
            const uint32_t b6off = (uint32_t)((((kk << 1) + b6half) ^ b6row) << 4);

            uint32_t bf[7][2];
            ldsm4(bf[0][0], bf[0][1], bf[1][0], bf[1][1], b_base[0] + boff);
            ldsm4(bf[2][0], bf[2][1], bf[3][0], bf[3][1], b_base[1] + boff);
            ldsm4(bf[4][0], bf[4][1], bf[5][0], bf[5][1], b_base[2] + boff);
            ldsm2(bf[6][0], bf[6][1], b_base6 + b6off);

            uint32_t af[4][4];
#pragma unroll
            for (int mt = 0; mt < 4; mt++)
                ldsm4(af[mt][0], af[mt][1], af[mt][2], af[mt][3], a_base[mt] + aoff);

#pragma unroll
            for (int mt = 0; mt < 4; mt++)
#pragma unroll
                for (int nt = 0; nt < 7; nt++)
                    mma16816(acc[mt][nt], af[mt][0], af[mt][1], af[mt][2], af[mt][3],
                             bf[nt][0], bf[nt][1]);
        }

        if (kc == NKC - 1) {  // fold into running row-max (mask padded cols)
            const int cb = nc * BN + nbase + ((lane & 3) << 1);
#pragma unroll
            for (int mt = 0; mt < 4; mt++)
#pragma unroll
                for (int nt = 0; nt < 7; nt++)
#pragma unroll
                    for (int j = 0; j < 4; j++) {
                        int col = cb + nt * 8 + (j & 1);
                        if (col < PP)
                            rmax[mt * 2 + (j >> 1)] =
                                fmaxf(rmax[mt * 2 + (j >> 1)], acc[mt][nt][j]);
                    }
        }
    }

    // reduce across the 4 lanes of each row-quad (disjoint cols)
#pragma unroll
    for (int o = 1; o <= 2; o <<= 1)
#pragma unroll
        for (int i = 0; i < 8; i++)
            rmax[i] = fmaxf(rmax[i], __shfl_xor_sync(0xffffffffu, rmax[i], o));

    float* rm = (float*)(smem + SM_RM);
    // nslot 0 writes, then nslot 1 merges
    if (nslot == 0 && (lane & 3) == 0) {
#pragma unroll
        for (int mt = 0; mt < 4; mt++)
#pragma unroll
            for (int h = 0; h < 2; h++) {
                int row = mslot * 64 + mt * 16 + h * 8 + (lane >> 2);
                if (row < PP) rm[row] = rmax[mt * 2 + h];
            }
    }
    __syncthreads();
    if (nslot == 1 && (lane & 3) == 0) {
#pragma unroll
        for (int mt = 0; mt < 4; mt++)
#pragma unroll
            for (int h = 0; h < 2; h++) {
                int row = mslot * 64 + mt * 16 + h * 8 + (lane >> 2);
                if (row < PP) rm[row] = fmaxf(rm[row], rmax[mt * 2 + h]);
            }
    }
    __syncthreads();

    // top-6 over 196 row-max values (warp 0)
    if (wid == 0) {
        float v[7];
#pragma unroll
        for (int k = 0; k < 7; k++) {
            int idx = lane + 32 * k;
            v[k] = (idx < PP) ? rm[idx] : NEG;
        }
        float sum = 0.f;
#pragma unroll
        for (int itk = 0; itk < 6; itk++) {
            float best = v[0]; int bslot = 0;
#pragma unroll
            for (int k = 1; k < 7; k++)
                if (v[k] > best) { best = v[k]; bslot = k; }
            int bid = lane;
#pragma unroll
            for (int o = 16; o; o >>= 1) {
                float ov = __shfl_xor_sync(0xffffffffu, best, o);
                int  oid = __shfl_xor_sync(0xffffffffu, bid, o);
                int  osl = __shfl_xor_sync(0xffffffffu, bslot, o);
                if (ov > best || (ov == best && oid < bid)) {
                    best = ov; bid = oid; bslot = osl;
                }
            }
            sum += best;
            if (lane == bid) v[bslot] = NEG;
        }
        if (lane == 0)
            out[m * NCLS + c] = scale_cls[0] * (sum + bias[0]);
    }
}

// ---------------- launch ----------------
extern "C" void kernel_launch(void* const* d_in, const int* in_sizes, int n_in,
                              void* d_out, int out_size)
{
    (void)in_sizes; (void)n_in; (void)out_size;
    const float* support   = (const float*)d_in[0];
    const float* query     = (const float*)d_in[1];
    const float* scale_cls = (const float*)d_in[2];
    const float* bias      = (const float*)d_in[3];
    float* out = (float*)d_out;

    int nrows = NROWS_Q + NROWS_S;
    norm_kernel<<<(nrows + 3) / 4, 128>>>(support, query);

    cudaFuncSetAttribute(protonet_kernel,
                         cudaFuncAttributeMaxDynamicSharedMemorySize, SMEM_BYTES);
    // grid.x = class (Sn tiny, L2-resident); grid.y = m so a wave shares Qn
    // rows across the 5 classes via L2.
    protonet_kernel<<<dim3(NCLS, MIMG), 256, SMEM_BYTES>>>(scale_cls, bias, out);
}

// round 8
// speedup vs baseline: 1.0209x; 1.0123x over previous
#include <cuda_runtime.h>
#include <cuda_bf16.h>
#include <cstdint>

// Problem shapes
#define NCLS 5
#define MIMG 512
#define PP   196
#define DD   384
#define NROWS_Q (MIMG * PP)
#define NROWS_S (NCLS * PP)

#define ROWB 768            // bytes per feature row (384 bf16)
#define NCHA 48             // 16B chunks per A row
#define AP   208            // physical padded A rows
#define BN   112            // B chunk columns (n per chunk)
#define BKB  256            // bytes per B row per k-chunk (128 k * 2B)
#define NNC  2              // n chunks (224 padded)
#define NKC  3              // k chunks of 128
#define NIT  (NNC * NKC)    // 6 pipeline iterations
#define NTHR 512

#define ASIZE (AP * ROWB)             // 159744
#define BSIZE (BN * BKB)              // 28672
#define SM_B0 ASIZE
#define SM_B1 (ASIZE + BSIZE)
#define SM_RM (ASIZE + 2 * BSIZE)     // 217088
#define SMEM_BYTES (SM_RM + AP * 4)   // 217920

// Normalized bf16 copies (device-global scratch: allowed)
__device__ __nv_bfloat16 g_QN[(size_t)NROWS_Q * DD];
__device__ __nv_bfloat16 g_SN[(size_t)NROWS_S * DD];

// ---------------- helpers ----------------
static __device__ __forceinline__ uint32_t smem_u32(const void* p) {
    uint32_t a;
    asm("{ .reg .u64 t; cvta.to.shared.u64 t, %1; cvt.u32.u64 %0, t; }" : "=r"(a) : "l"(p));
    return a;
}

static __device__ __forceinline__ void cp16(uint32_t dst, const void* src) {
    asm volatile("cp.async.cg.shared.global [%0], [%1], 16;"
                 :: "r"(dst), "l"(src) : "memory");
}
#define CP_COMMIT() asm volatile("cp.async.commit_group;" ::: "memory")
#define CP_WAIT0()  asm volatile("cp.async.wait_group 0;" ::: "memory")
#define CP_WAIT1()  asm volatile("cp.async.wait_group 1;" ::: "memory")

static __device__ __forceinline__ void ldsm4(uint32_t& d0, uint32_t& d1,
                                             uint32_t& d2, uint32_t& d3, uint32_t addr) {
    asm volatile("ldmatrix.sync.aligned.m8n8.x4.shared.b16 {%0,%1,%2,%3}, [%4];"
                 : "=r"(d0), "=r"(d1), "=r"(d2), "=r"(d3) : "r"(addr));
}
static __device__ __forceinline__ void ldsm2(uint32_t& d0, uint32_t& d1, uint32_t addr) {
    asm volatile("ldmatrix.sync.aligned.m8n8.x2.shared.b16 {%0,%1}, [%2];"
                 : "=r"(d0), "=r"(d1) : "r"(addr));
}

static __device__ __forceinline__ void mma16816(float* c,
        uint32_t a0, uint32_t a1, uint32_t a2, uint32_t a3,
        uint32_t b0, uint32_t b1) {
    asm volatile(
        "mma.sync.aligned.m16n8k16.row.col.f32.bf16.bf16.f32 "
        "{%0,%1,%2,%3}, {%4,%5,%6,%7}, {%8,%9}, {%0,%1,%2,%3};"
        : "+f"(c[0]), "+f"(c[1]), "+f"(c[2]), "+f"(c[3])
        : "r"(a0), "r"(a1), "r"(a2), "r"(a3), "r"(b0), "r"(b1));
}

// ---------------- Kernel 1: L2-normalize rows -> bf16 ----------------
__global__ __launch_bounds__(128) void norm_kernel(
    const float* __restrict__ support, const float* __restrict__ query)
{
    int row  = blockIdx.x * 4 + (threadIdx.x >> 5);
    int lane = threadIdx.x & 31;
    const float* src;
    __nv_bfloat16* dst;
    if (row < NROWS_Q) {
        src = query + (size_t)row * DD;
        dst = g_QN  + (size_t)row * DD;
    } else {
        int r = row - NROWS_Q;
        if (r >= NROWS_S) return;
        src = support + (size_t)r * DD;
        dst = g_SN    + (size_t)r * DD;
    }
    const float4* s4 = (const float4*)src;
    float4 v[3];
    float ss = 0.f;
#pragma unroll
    for (int j = 0; j < 3; j++) {
        v[j] = s4[lane * 3 + j];
        ss += v[j].x * v[j].x + v[j].y * v[j].y + v[j].z * v[j].z + v[j].w * v[j].w;
    }
#pragma unroll
    for (int o = 16; o; o >>= 1) ss += __shfl_xor_sync(0xffffffffu, ss, o);
    float inv = 1.0f / fmaxf(sqrtf(ss), 1e-12f);

    uint2* d2 = (uint2*)dst;
#pragma unroll
    for (int j = 0; j < 3; j++) {
        __nv_bfloat162 h0 = __floats2bfloat162_rn(v[j].x * inv, v[j].y * inv);
        __nv_bfloat162 h1 = __floats2bfloat162_rn(v[j].z * inv, v[j].w * inv);
        uint2 u;
        u.x = *reinterpret_cast<uint32_t*>(&h0);
        u.y = *reinterpret_cast<uint32_t*>(&h1);
        d2[lane * 3 + j] = u;
    }
}

// ---------------- Kernel 2: per-(m,c) GEMM + rowmax + top-6 ----------------
// 16 warps = 8 M-slots (32 rows, 2 x m16) x 2 N-slots (56 cols, 7 x n8).
// M padded to 256 logically; physical A smem has 208 rows, phantom tiles
// alias rows 192-207 (outputs discarded via row<196 guard).
// N padded to 224 = 2 chunks of 112. K = 3 chunks of 128, B double-buffered.
__global__ __launch_bounds__(NTHR, 1) void protonet_kernel(
    const float* __restrict__ scale_cls, const float* __restrict__ bias,
    float* __restrict__ out)
{
    extern __shared__ char smem[];
    const uint32_t sb = smem_u32(smem);
    const int tid = threadIdx.x, wid = tid >> 5, lane = tid & 31;
    const int c = blockIdx.x, m = blockIdx.y;
    const int mslot = wid >> 1;          // 0..7
    const int nslot = wid & 1;           // 0..1
    const int nbase = nslot * 56;

    const char* qg = (const char*)(g_QN + (size_t)m * PP * DD);
    const char* sg = (const char*)(g_SN + (size_t)c * PP * DD);

    // ---- prologue: A (full K, 208 rows) + B(it0) as group0, B(it1) as group1
    for (int i = tid; i < AP * NCHA; i += NTHR) {
        int r = i / NCHA, ch = i % NCHA;
        int rc = r < PP ? r : PP - 1;
        cp16(sb + (uint32_t)r * ROWB + (uint32_t)((ch ^ (r & 7)) << 4),
             qg + (size_t)rc * ROWB + (ch << 4));
    }
    {   // B it0: nc=0, kc=0 -> buf0
        for (int i = tid; i < BN * 16; i += NTHR) {
            int r = i >> 4, ch = i & 15;
            int q = r < PP ? r : PP - 1;
            cp16(sb + SM_B0 + (uint32_t)r * BKB + (uint32_t)((ch ^ (r & 7)) << 4),
                 sg + (size_t)q * ROWB + (ch << 4));
        }
    }
    CP_COMMIT();
    {   // B it1: nc=0, kc=1 -> buf1
        for (int i = tid; i < BN * 16; i += NTHR) {
            int r = i >> 4, ch = i & 15;
            int q = r < PP ? r : PP - 1;
            cp16(sb + SM_B1 + (uint32_t)r * BKB + (uint32_t)((ch ^ (r & 7)) << 4),
                 sg + (size_t)q * ROWB + 256 + (ch << 4));
        }
    }
    CP_COMMIT();

    // ---- fragment addressing ----
    const int lm = lane >> 3, lr = lane & 7;
    const int arow  = ((lm & 1) << 3) + lr;   // A ldsm: (r0-7,k0)(r8-15,k0)(r0-7,k1)(r8-15,k1)
    const int ahalf = lm >> 1;
    const int brow  = ((lm >> 1) << 3) + lr;  // B ldsm x4: (n0-7,k0)(n0-7,k1)(n8-15,k0)(n8-15,k1)
    const int bhalf = lm & 1;
    const int b6row = lane & 7;               // B ldsm x2 (lanes 0-15 meaningful)
    const int b6half = (lane >> 3) & 1;

    uint32_t a_base[2];
#pragma unroll
    for (int mt = 0; mt < 2; mt++) {
        int rb = mslot * 32 + mt * 16;
        if (rb > 192) rb = 192;               // phantom tiles alias rows 192-207
        a_base[mt] = sb + (uint32_t)(rb + arow) * ROWB;
    }

    const float NEG = __int_as_float(0xff800000);
    float rmax[4];
#pragma unroll
    for (int i = 0; i < 4; i++) rmax[i] = NEG;

    float acc[2][7][4];

#pragma unroll 1
    for (int it = 0; it < NIT; it++) {
        const int nc = it / NKC, kc = it - nc * NKC;
        if (kc == 0) {
#pragma unroll
            for (int mt = 0; mt < 2; mt++)
#pragma unroll
                for (int nt = 0; nt < 7; nt++)
#pragma unroll
                    for (int j = 0; j < 4; j++) acc[mt][nt][j] = 0.f;
        }

        if (it < NIT - 1) CP_WAIT1(); else CP_WAIT0();
        __syncthreads();

        if (it + 1 < NIT) {   // prefetch B for it+1 into the other buffer
            int nit = it + 1;
            int nnc = nit / NKC, nkc = nit - nnc * NKC;
            uint32_t bb = sb + ((nit & 1) ? SM_B1 : SM_B0);
            for (int i = tid; i < BN * 16; i += NTHR) {
                int r = i >> 4, ch = i & 15;
                int q = nnc * BN + r;
                if (q > PP - 1) q = PP - 1;
                cp16(bb + (uint32_t)r * BKB + (uint32_t)((ch ^ (r & 7)) << 4),
                     sg + (size_t)q * ROWB + nkc * 256 + (ch << 4));
            }
            CP_COMMIT();
        }

        const uint32_t bbuf = sb + ((it & 1) ? SM_B1 : SM_B0);
        uint32_t b_base[3], b_base6;
#pragma unroll
        for (int p = 0; p < 3; p++)
            b_base[p] = bbuf + (uint32_t)(nbase + p * 16 + brow) * BKB;
        b_base6 = bbuf + (uint32_t)(nbase + 48 + b6row) * BKB;

#pragma unroll
        for (int kk = 0; kk < 8; kk++) {
            const int ks = kc * 8 + kk;
            const uint32_t aoff = (uint32_t)((((ks << 1) + ahalf) ^ lr) << 4);
            const uint32_t boff = (uint32_t)((((kk << 1) + bhalf) ^ lr) << 4);
            const uint32_t b6off = (uint32_t)((((kk << 1) + b6half) ^ b6row) << 4);

            uint32_t bf[7][2];
            ldsm4(bf[0][0], bf[0][1], bf[1][0], bf[1][1], b_base[0] + boff);
            ldsm4(bf[2][0], bf[2][1], bf[3][0], bf[3][1], b_base[1] + boff);
            ldsm4(bf[4][0], bf[4][1], bf[5][0], bf[5][1], b_base[2] + boff);
            ldsm2(bf[6][0], bf[6][1], b_base6 + b6off);

            uint32_t af[2][4];
#pragma unroll
            for (int mt = 0; mt < 2; mt++)
                ldsm4(af[mt][0], af[mt][1], af[mt][2], af[mt][3], a_base[mt] + aoff);

#pragma unroll
            for (int mt = 0; mt < 2; mt++)
#pragma unroll
                for (int nt = 0; nt < 7; nt++)
                    mma16816(acc[mt][nt], af[mt][0], af[mt][1], af[mt][2], af[mt][3],
                             bf[nt][0], bf[nt][1]);
        }

        if (kc == NKC - 1) {  // fold into running row-max (mask padded cols)
            const int cb = nc * BN + nbase + ((lane & 3) << 1);
#pragma unroll
            for (int mt = 0; mt < 2; mt++)
#pragma unroll
                for (int nt = 0; nt < 7; nt++)
#pragma unroll
                    for (int j = 0; j < 4; j++) {
                        int col = cb + nt * 8 + (j & 1);
                        if (col < PP)
                            rmax[mt * 2 + (j >> 1)] =
                                fmaxf(rmax[mt * 2 + (j >> 1)], acc[mt][nt][j]);
                    }
        }
    }

    // reduce across the 4 lanes of each row-quad (disjoint cols)
#pragma unroll
    for (int o = 1; o <= 2; o <<= 1)
#pragma unroll
        for (int i = 0; i < 4; i++)
            rmax[i] = fmaxf(rmax[i], __shfl_xor_sync(0xffffffffu, rmax[i], o));

    float* rm = (float*)(smem + SM_RM);
    // nslot 0 writes, then nslot 1 merges
    if (nslot == 0 && (lane & 3) == 0) {
#pragma unroll
        for (int mt = 0; mt < 2; mt++)
#pragma unroll
            for (int h = 0; h < 2; h++) {
                int row = mslot * 32 + mt * 16 + h * 8 + (lane >> 2);
                if (row < PP) rm[row] = rmax[mt * 2 + h];
            }
    }
    __syncthreads();
    if (nslot == 1 && (lane & 3) == 0) {
#pragma unroll
        for (int mt = 0; mt < 2; mt++)
#pragma unroll
            for (int h = 0; h < 2; h++) {
                int row = mslot * 32 + mt * 16 + h * 8 + (lane >> 2);
                if (row < PP) rm[row] = fmaxf(rm[row], rmax[mt * 2 + h]);
            }
    }
    __syncthreads();

    // top-6 over 196 row-max values (warp 0)
    if (wid == 0) {
        float v[7];
#pragma unroll
        for (int k = 0; k < 7; k++) {
            int idx = lane + 32 * k;
            v[k] = (idx < PP) ? rm[idx] : NEG;
        }
        float sum = 0.f;
#pragma unroll
        for (int itk = 0; itk < 6; itk++) {
            float best = v[0]; int bslot = 0;
#pragma unroll
            for (int k = 1; k < 7; k++)
                if (v[k] > best) { best = v[k]; bslot = k; }
            int bid = lane;
#pragma unroll
            for (int o = 16; o; o >>= 1) {
                float ov = __shfl_xor_sync(0xffffffffu, best, o);
                int  oid = __shfl_xor_sync(0xffffffffu, bid, o);
                int  osl = __shfl_xor_sync(0xffffffffu, bslot, o);
                if (ov > best || (ov == best && oid < bid)) {
                    best = ov; bid = oid; bslot = osl;
                }
            }
            sum += best;
            if (lane == bid) v[bslot] = NEG;
        }
        if (lane == 0)
            out[m * NCLS + c] = scale_cls[0] * (sum + bias[0]);
    }
}

// ---------------- launch ----------------
extern "C" void kernel_launch(void* const* d_in, const int* in_sizes, int n_in,
                              void* d_out, int out_size)
{
    (void)in_sizes; (void)n_in; (void)out_size;
    const float* support   = (const float*)d_in[0];
    const float* query     = (const float*)d_in[1];
    const float* scale_cls = (const float*)d_in[2];
    const float* bias      = (const float*)d_in[3];
    float* out = (float*)d_out;

    int nrows = NROWS_Q + NROWS_S;
    norm_kernel<<<(nrows + 3) / 4, 128>>>(support, query);

    cudaFuncSetAttribute(protonet_kernel,
                         cudaFuncAttributeMaxDynamicSharedMemorySize, SMEM_BYTES);
    // grid.x = class (Sn tiny, L2-resident); grid.y = m so a wave shares Qn
    // rows across the 5 classes via L2.
    protonet_kernel<<<dim3(NCLS, MIMG), NTHR, SMEM_BYTES>>>(scale_cls, bias, out);
}

// round 9
// speedup vs baseline: 1.0967x; 1.0743x over previous
#include <cuda_runtime.h>
#include <cuda_bf16.h>
#include <cstdint>

// Problem shapes
#define NCLS 5
#define MIMG 512
#define PP   196
#define DD   384
#define NROWS_Q (MIMG * PP)
#define NROWS_S (NCLS * PP)

#define ROWB 768            // bytes per feature row (384 bf16)
#define NCHA 48             // 16B chunks per A row
#define AP   208            // physical padded A rows (13 x 16)
#define BN   112            // B chunk columns (n per chunk)
#define BKB  256            // bytes per B row per k-chunk (128 k * 2B)
#define NNC  2              // n chunks (224 padded)
#define NKC  3              // k chunks of 128
#define NIT  (NNC * NKC)    // 6 pipeline iterations
#define NTHR 512

#define ASIZE (AP * ROWB)             // 159744
#define BSIZE (BN * BKB)              // 28672
#define SM_B0 ASIZE
#define SM_B1 (ASIZE + BSIZE)
#define SM_RM (ASIZE + 2 * BSIZE)     // 217088
#define SMEM_BYTES (SM_RM + AP * 4)   // 217920

// Normalized bf16 copies (device-global scratch: allowed)
__device__ __nv_bfloat16 g_QN[(size_t)NROWS_Q * DD];
__device__ __nv_bfloat16 g_SN[(size_t)NROWS_S * DD];

// ---------------- helpers ----------------
static __device__ __forceinline__ uint32_t smem_u32(const void* p) {
    uint32_t a;
    asm("{ .reg .u64 t; cvta.to.shared.u64 t, %1; cvt.u32.u64 %0, t; }" : "=r"(a) : "l"(p));
    return a;
}

static __device__ __forceinline__ void cp16(uint32_t dst, const void* src) {
    asm volatile("cp.async.cg.shared.global [%0], [%1], 16;"
                 :: "r"(dst), "l"(src) : "memory");
}
#define CP_COMMIT() asm volatile("cp.async.commit_group;" ::: "memory")
#define CP_WAIT(n)  asm volatile("cp.async.wait_group %0;" :: "n"(n) : "memory")

static __device__ __forceinline__ void ldsm4(uint32_t& d0, uint32_t& d1,
                                             uint32_t& d2, uint32_t& d3, uint32_t addr) {
    asm volatile("ldmatrix.sync.aligned.m8n8.x4.shared.b16 {%0,%1,%2,%3}, [%4];"
                 : "=r"(d0), "=r"(d1), "=r"(d2), "=r"(d3) : "r"(addr));
}
static __device__ __forceinline__ void ldsm2(uint32_t& d0, uint32_t& d1, uint32_t addr) {
    asm volatile("ldmatrix.sync.aligned.m8n8.x2.shared.b16 {%0,%1}, [%2];"
                 : "=r"(d0), "=r"(d1) : "r"(addr));
}

static __device__ __forceinline__ void mma16816(float* c,
        uint32_t a0, uint32_t a1, uint32_t a2, uint32_t a3,
        uint32_t b0, uint32_t b1) {
    asm volatile(
        "mma.sync.aligned.m16n8k16.row.col.f32.bf16.bf16.f32 "
        "{%0,%1,%2,%3}, {%4,%5,%6,%7}, {%8,%9}, {%0,%1,%2,%3};"
        : "+f"(c[0]), "+f"(c[1]), "+f"(c[2]), "+f"(c[3])
        : "r"(a0), "r"(a1), "r"(a2), "r"(a3), "r"(b0), "r"(b1));
}

// ---------------- Kernel 1: L2-normalize rows -> bf16 ----------------
__global__ __launch_bounds__(128) void norm_kernel(
    const float* __restrict__ support, const float* __restrict__ query)
{
    int row  = blockIdx.x * 4 + (threadIdx.x >> 5);
    int lane = threadIdx.x & 31;
    const float* src;
    __nv_bfloat16* dst;
    if (row < NROWS_Q) {
        src = query + (size_t)row * DD;
        dst = g_QN  + (size_t)row * DD;
    } else {
        int r = row - NROWS_Q;
        if (r >= NROWS_S) return;
        src = support + (size_t)r * DD;
        dst = g_SN    + (size_t)r * DD;
    }
    const float4* s4 = (const float4*)src;
    float4 v[3];
    float ss = 0.f;
#pragma unroll
    for (int j = 0; j < 3; j++) {
        v[j] = s4[lane * 3 + j];
        ss += v[j].x * v[j].x + v[j].y * v[j].y + v[j].z * v[j].z + v[j].w * v[j].w;
    }
#pragma unroll
    for (int o = 16; o; o >>= 1) ss += __shfl_xor_sync(0xffffffffu, ss, o);
    float inv = 1.0f / fmaxf(sqrtf(ss), 1e-12f);

    uint2* d2 = (uint2*)dst;
#pragma unroll
    for (int j = 0; j < 3; j++) {
        __nv_bfloat162 h0 = __floats2bfloat162_rn(v[j].x * inv, v[j].y * inv);
        __nv_bfloat162 h1 = __floats2bfloat162_rn(v[j].z * inv, v[j].w * inv);
        uint2 u;
        u.x = *reinterpret_cast<uint32_t*>(&h0);
        u.y = *reinterpret_cast<uint32_t*>(&h1);
        d2[lane * 3 + j] = u;
    }
}

// ---------------- per-iteration kstep compute (MT = #m16 tiles) ----------------
template <int MT>
static __device__ __forceinline__ void do_ksteps(
    const uint32_t a_base[2], const uint32_t b_base[3], uint32_t b_base6,
    int kc, int lr, int ahalf, int bhalf, int b6half, int b6row,
    float acc[2][7][4])
{
#pragma unroll
    for (int kk = 0; kk < 8; kk++) {
        const int ks = kc * 8 + kk;
        const uint32_t aoff = (uint32_t)((((ks << 1) + ahalf) ^ lr) << 4);
        const uint32_t boff = (uint32_t)((((kk << 1) + bhalf) ^ lr) << 4);
        const uint32_t b6off = (uint32_t)((((kk << 1) + b6half) ^ b6row) << 4);

        uint32_t bf[7][2];
        ldsm4(bf[0][0], bf[0][1], bf[1][0], bf[1][1], b_base[0] + boff);
        ldsm4(bf[2][0], bf[2][1], bf[3][0], bf[3][1], b_base[1] + boff);
        ldsm4(bf[4][0], bf[4][1], bf[5][0], bf[5][1], b_base[2] + boff);
        ldsm2(bf[6][0], bf[6][1], b_base6 + b6off);

        uint32_t af[MT][4];
#pragma unroll
        for (int mt = 0; mt < MT; mt++)
            ldsm4(af[mt][0], af[mt][1], af[mt][2], af[mt][3], a_base[mt] + aoff);

#pragma unroll
        for (int mt = 0; mt < MT; mt++)
#pragma unroll
            for (int nt = 0; nt < 7; nt++)
                mma16816(acc[mt][nt], af[mt][0], af[mt][1], af[mt][2], af[mt][3],
                         bf[nt][0], bf[nt][1]);
    }
}

// ---------------- Kernel 2: per-(m,c) GEMM + rowmax + top-6 ----------------
// 14 compute warps = 7 M-slots (slots 0-5: 32 rows, slot 6: 16 rows -> M=208
// exact, no phantom tiles) x 2 N-slots (56 cols). Warps 14-15: cp.async only.
// N padded to 224 = 2 chunks of 112. K = 3 chunks of 128, B double-buffered
// at prefetch distance 2 (B_{i+2} issued after end-of-iteration barrier).
// A prologue split by k-chunk so it0 starts after 81KB, not 188KB.
__global__ __launch_bounds__(NTHR, 1) void protonet_kernel(
    const float* __restrict__ scale_cls, const float* __restrict__ bias,
    float* __restrict__ out)
{
    extern __shared__ char smem[];
    const uint32_t sb = smem_u32(smem);
    const int tid = threadIdx.x, wid = tid >> 5, lane = tid & 31;
    const int c = blockIdx.x, m = blockIdx.y;
    const int mslot = wid >> 1;          // 0..7 (7 = inactive)
    const int nslot = wid & 1;
    const int nbase = nslot * 56;
    const int MT = (mslot < 6) ? 2 : ((mslot == 6) ? 1 : 0);

    const char* qg = (const char*)(g_QN + (size_t)m * PP * DD);
    const char* sg = (const char*)(g_SN + (size_t)c * PP * DD);

    // ---- prologue: G0 = {A_k0, B_it0}, G1 = {A_k1, B_it1}, G2 = {A_k2} ----
#pragma unroll 1
    for (int kc = 0; kc < NKC; kc++) {
        for (int i = tid; i < AP * 16; i += NTHR) {
            int r = i >> 4, ch = kc * 16 + (i & 15);
            int rc = r < PP ? r : PP - 1;
            cp16(sb + (uint32_t)r * ROWB + (uint32_t)((ch ^ (r & 7)) << 4),
                 qg + (size_t)rc * ROWB + (ch << 4));
        }
        if (kc < 2) {   // B for iteration kc (nc=0, k-chunk kc) -> buf kc
            uint32_t bb = sb + (kc ? SM_B1 : SM_B0);
            for (int i = tid; i < BN * 16; i += NTHR) {
                int r = i >> 4, ch = i & 15;
                int q = r < PP ? r : PP - 1;
                cp16(bb + (uint32_t)r * BKB + (uint32_t)((ch ^ (r & 7)) << 4),
                     sg + (size_t)q * ROWB + kc * 256 + (ch << 4));
            }
        }
        CP_COMMIT();
    }

    // ---- fragment addressing ----
    const int lm = lane >> 3, lr = lane & 7;
    const int arow  = ((lm & 1) << 3) + lr;
    const int ahalf = lm >> 1;
    const int brow  = ((lm >> 1) << 3) + lr;
    const int bhalf = lm & 1;
    const int b6row = lane & 7;
    const int b6half = (lane >> 3) & 1;

    uint32_t a_base[2];
#pragma unroll
    for (int mt = 0; mt < 2; mt++) {
        int rb = mslot * 32 + mt * 16;
        if (rb > 192) rb = 192;          // only reached by inactive/MT=1 unused slots
        a_base[mt] = sb + (uint32_t)(rb + arow) * ROWB;
    }

    const float NEG = __int_as_float(0xff800000);
    float rmax[4];
#pragma unroll
    for (int i = 0; i < 4; i++) rmax[i] = NEG;

    float acc[2][7][4];

#pragma unroll 1
    for (int it = 0; it < NIT; it++) {
        const int nc = it / NKC, kc = it - nc * NKC;
        if (kc == 0) {
#pragma unroll
            for (int mt = 0; mt < 2; mt++)
#pragma unroll
                for (int nt = 0; nt < 7; nt++)
#pragma unroll
                    for (int j = 0; j < 4; j++) acc[mt][nt][j] = 0.f;
        }

        // group schedule: it0/it1 need G_it (2 newer pending); it2-4 need
        // G_{it+1} with commits up to G_{it+2} -> 1 pending; it5 -> 0.
        if (it < 2)      CP_WAIT(2);
        else if (it < 5) CP_WAIT(1);
        else             CP_WAIT(0);
        __syncthreads();

        const uint32_t bbuf = sb + ((it & 1) ? SM_B1 : SM_B0);
        uint32_t b_base[3], b_base6;
#pragma unroll
        for (int p = 0; p < 3; p++)
            b_base[p] = bbuf + (uint32_t)(nbase + p * 16 + brow) * BKB;
        b_base6 = bbuf + (uint32_t)(nbase + 48 + b6row) * BKB;

        if (MT == 2)
            do_ksteps<2>(a_base, b_base, b_base6, kc, lr, ahalf, bhalf, b6half, b6row, acc);
        else if (MT == 1)
            do_ksteps<1>(a_base, b_base, b_base6, kc, lr, ahalf, bhalf, b6half, b6row, acc);

        if (kc == NKC - 1 && MT) {  // fold into running row-max (mask padded cols)
            const int cb = nc * BN + nbase + ((lane & 3) << 1);
#pragma unroll
            for (int mt = 0; mt < 2; mt++) {
                if (mt >= MT) break;
#pragma unroll
                for (int nt = 0; nt < 7; nt++)
#pragma unroll
                    for (int j = 0; j < 4; j++) {
                        int col = cb + nt * 8 + (j & 1);
                        if (col < PP)
                            rmax[mt * 2 + (j >> 1)] =
                                fmaxf(rmax[mt * 2 + (j >> 1)], acc[mt][nt][j]);
                    }
            }
        }

        if (it + 2 < NIT) {   // prefetch B_{it+2} into buf(it&1) after all read it
            __syncthreads();
            int nit = it + 2;
            int nnc = nit / NKC, nkc = nit - nnc * NKC;
            for (int i = tid; i < BN * 16; i += NTHR) {
                int r = i >> 4, ch = i & 15;
                int q = nnc * BN + r;
                if (q > PP - 1) q = PP - 1;
                cp16(bbuf + (uint32_t)r * BKB + (uint32_t)((ch ^ (r & 7)) << 4),
                     sg + (size_t)q * ROWB + nkc * 256 + (ch << 4));
            }
            CP_COMMIT();
        }
    }

    // reduce across the 4 lanes of each row-quad (disjoint cols)
#pragma unroll
    for (int o = 1; o <= 2; o <<= 1)
#pragma unroll
        for (int i = 0; i < 4; i++)
            rmax[i] = fmaxf(rmax[i], __shfl_xor_sync(0xffffffffu, rmax[i], o));

    float* rm = (float*)(smem + SM_RM);
    // nslot 0 writes, then nslot 1 merges
    if (MT && nslot == 0 && (lane & 3) == 0) {
#pragma unroll
        for (int mt = 0; mt < 2; mt++) {
            if (mt >= MT) break;
#pragma unroll
            for (int h = 0; h < 2; h++) {
                int row = mslot * 32 + mt * 16 + h * 8 + (lane >> 2);
                if (row < PP) rm[row] = rmax[mt * 2 + h];
            }
        }
    }
    __syncthreads();
    if (MT && nslot == 1 && (lane & 3) == 0) {
#pragma unroll
        for (int mt = 0; mt < 2; mt++) {
            if (mt >= MT) break;
#pragma unroll
            for (int h = 0; h < 2; h++) {
                int row = mslot * 32 + mt * 16 + h * 8 + (lane >> 2);
                if (row < PP) rm[row] = fmaxf(rm[row], rmax[mt * 2 + h]);
            }
        }
    }
    __syncthreads();

    // top-6 over 196 row-max values (warp 0)
    if (wid == 0) {
        float v[7];
#pragma unroll
        for (int k = 0; k < 7; k++) {
            int idx = lane + 32 * k;
            v[k] = (idx < PP) ? rm[idx] : NEG;
        }
        float sum = 0.f;
#pragma unroll
        for (int itk = 0; itk < 6; itk++) {
            float best = v[0]; int bslot = 0;
#pragma unroll
            for (int k = 1; k < 7; k++)
                if (v[k] > best) { best = v[k]; bslot = k; }
            int bid = lane;
#pragma unroll
            for (int o = 16; o; o >>= 1) {
                float ov = __shfl_xor_sync(0xffffffffu, best, o);
                int  oid = __shfl_xor_sync(0xffffffffu, bid, o);
                int  osl = __shfl_xor_sync(0xffffffffu, bslot, o);
                if (ov > best || (ov == best && oid < bid)) {
                    best = ov; bid = oid; bslot = osl;
                }
            }
            sum += best;
            if (lane == bid) v[bslot] = NEG;
        }
        if (lane == 0)
            out[m * NCLS + c] = scale_cls[0] * (sum + bias[0]);
    }
}

// ---------------- launch ----------------
extern "C" void kernel_launch(void* const* d_in, const int* in_sizes, int n_in,
                              void* d_out, int out_size)
{
    (void)in_sizes; (void)n_in; (void)out_size;
    const float* support   = (const float*)d_in[0];
    const float* query     = (const float*)d_in[1];
    const float* scale_cls = (const float*)d_in[2];
    const float* bias      = (const float*)d_in[3];
    float* out = (float*)d_out;

    int nrows = NROWS_Q + NROWS_S;
    norm_kernel<<<(nrows + 3) / 4, 128>>>(support, query);

    cudaFuncSetAttribute(protonet_kernel,
                         cudaFuncAttributeMaxDynamicSharedMemorySize, SMEM_BYTES);
    // grid.x = class (Sn tiny, L2-resident); grid.y = m so a wave shares Qn
    // rows across the 5 classes via L2.
    protonet_kernel<<<dim3(NCLS, MIMG), NTHR, SMEM_BYTES>>>(scale_cls, bias, out);
}

// round 13
// speedup vs baseline: 1.2081x; 1.1015x over previous
#include <cuda_runtime.h>
#include <cuda_bf16.h>
#include <cstdint>

// Problem shapes
#define NCLS 5
#define MIMG 512
#define PP   196
#define DD   384
#define NROWS_Q (MIMG * PP)
#define NROWS_S (NCLS * PP)

#define ROWB 768            // bytes per feature row (384 bf16)
#define AP   208            // physical padded A rows (13 x 16)
#define BKB  256            // bytes per B row per k-chunk (128 k * 2B)
#define BN0  112            // n-chunk 0 width
#define BN1  88             // n-chunk 1 width (200 total = 25 x n8, min pad)
#define NKC  3              // k chunks of 128
#define NIT  6              // (2 n-chunks) x (3 k-chunks)
#define NTHR 512
#define NCW  448            // compute threads (14 warps)

#define ASIZE (AP * ROWB)             // 159744
#define BSIZE (BN0 * BKB)             // 28672 (buffer sized for widest chunk)
#define SM_B0 ASIZE
#define SM_B1 (ASIZE + BSIZE)
#define SM_RM (ASIZE + 2 * BSIZE)     // 217088
#define SM_MB (SM_RM + AP * 4)        // 217920 (2 mbarriers, 16B)
#define SMEM_BYTES (SM_MB + 16)       // 217936

// Normalized bf16 copies (device-global scratch: allowed)
__device__ __nv_bfloat16 g_QN[(size_t)NROWS_Q * DD];
__device__ __nv_bfloat16 g_SN[(size_t)NROWS_S * DD];

// ---------------- helpers ----------------
static __device__ __forceinline__ uint32_t smem_u32(const void* p) {
    uint32_t a;
    asm("{ .reg .u64 t; cvta.to.shared.u64 t, %1; cvt.u32.u64 %0, t; }" : "=r"(a) : "l"(p));
    return a;
}

static __device__ __forceinline__ void cp16(uint32_t dst, const void* src) {
    asm volatile("cp.async.cg.shared.global [%0], [%1], 16;"
                 :: "r"(dst), "l"(src) : "memory");
}
#define CP_COMMIT() asm volatile("cp.async.commit_group;" ::: "memory")
#define CP_WAIT(n)  asm volatile("cp.async.wait_group %0;" :: "n"(n) : "memory")

#define MBAR_INIT(addr, cnt) \
    asm volatile("mbarrier.init.shared.b64 [%0], %1;" :: "r"(addr), "r"(cnt) : "memory")

#define MBAR_WAIT(addr, phase) do { \
    uint32_t _m = (addr); uint32_t _ph = (phase); uint32_t _done; \
    asm volatile("{\n\t.reg .pred p;\n\t" \
        "mbarrier.try_wait.parity.shared.b64 p, [%1], %2;\n\t" \
        "selp.b32 %0, 1, 0, p;\n\t}" \
        : "=r"(_done) : "r"(_m), "r"(_ph) : "memory"); \
    if (!_done) { \
        asm volatile("{\n\t.reg .pred P1;\n\t" \
            "WL_%=:\n\t" \
            "mbarrier.try_wait.parity.shared.b64 P1, [%0], %1;\n\t" \
            "@P1 bra.uni WD_%=;\n\t" \
            "bra.uni WL_%=;\n\t" \
            "WD_%=:\n\t}" \
            :: "r"(_m), "r"(_ph) : "memory"); \
    } \
} while (0)

// cp.async completions (this thread) arrive on mbarrier (preset count)
#define CPASYNC_MBAR_ARRIVE(addr) \
    asm volatile("cp.async.mbarrier.arrive.noinc.shared.b64 [%0];" \
                 :: "r"(addr) : "memory")

#define BAR_ARRIVE(id, cnt) \
    asm volatile("bar.arrive %0, %1;" :: "r"(id), "r"(cnt) : "memory")
#define BAR_SYNC(id, cnt) \
    asm volatile("bar.sync %0, %1;" :: "r"(id), "r"(cnt) : "memory")

static __device__ __forceinline__ void ldsm4(uint32_t& d0, uint32_t& d1,
                                             uint32_t& d2, uint32_t& d3, uint32_t addr) {
    asm volatile("ldmatrix.sync.aligned.m8n8.x4.shared.b16 {%0,%1,%2,%3}, [%4];"
                 : "=r"(d0), "=r"(d1), "=r"(d2), "=r"(d3) : "r"(addr));
}
static __device__ __forceinline__ void ldsm2(uint32_t& d0, uint32_t& d1, uint32_t addr) {
    asm volatile("ldmatrix.sync.aligned.m8n8.x2.shared.b16 {%0,%1}, [%2];"
                 : "=r"(d0), "=r"(d1) : "r"(addr));
}

static __device__ __forceinline__ void mma16816(float* c,
        uint32_t a0, uint32_t a1, uint32_t a2, uint32_t a3,
        uint32_t b0, uint32_t b1) {
    asm volatile(
        "mma.sync.aligned.m16n8k16.row.col.f32.bf16.bf16.f32 "
        "{%0,%1,%2,%3}, {%4,%5,%6,%7}, {%8,%9}, {%0,%1,%2,%3};"
        : "+f"(c[0]), "+f"(c[1]), "+f"(c[2]), "+f"(c[3])
        : "r"(a0), "r"(a1), "r"(a2), "r"(a3), "r"(b0), "r"(b1));
}

// ---------------- Kernel 1: L2-normalize rows -> bf16 ----------------
__global__ __launch_bounds__(128) void norm_kernel(
    const float* __restrict__ support, const float* __restrict__ query)
{
    int row  = blockIdx.x * 4 + (threadIdx.x >> 5);
    int lane = threadIdx.x & 31;
    const float* src;
    __nv_bfloat16* dst;
    if (row < NROWS_Q) {
        src = query + (size_t)row * DD;
        dst = g_QN  + (size_t)row * DD;
    } else {
        int r = row - NROWS_Q;
        if (r >= NROWS_S) return;
        src = support + (size_t)r * DD;
        dst = g_SN    + (size_t)r * DD;
    }
    const float4* s4 = (const float4*)src;
    float4 v[3];
    float ss = 0.f;
#pragma unroll
    for (int j = 0; j < 3; j++) {
        v[j] = s4[lane * 3 + j];
        ss += v[j].x * v[j].x + v[j].y * v[j].y + v[j].z * v[j].z + v[j].w * v[j].w;
    }
#pragma unroll
    for (int o = 16; o; o >>= 1) ss += __shfl_xor_sync(0xffffffffu, ss, o);
    float inv = 1.0f / fmaxf(sqrtf(ss), 1e-12f);

    uint2* d2 = (uint2*)dst;
#pragma unroll
    for (int j = 0; j < 3; j++) {
        __nv_bfloat162 h0 = __floats2bfloat162_rn(v[j].x * inv, v[j].y * inv);
        __nv_bfloat162 h1 = __floats2bfloat162_rn(v[j].z * inv, v[j].w * inv);
        uint2 u;
        u.x = *reinterpret_cast<uint32_t*>(&h0);
        u.y = *reinterpret_cast<uint32_t*>(&h1);
        d2[lane * 3 + j] = u;
    }
}

// ---------------- per-iteration kstep compute ----------------
template <int MT, int NT>
static __device__ __forceinline__ void do_ksteps(
    const uint32_t a_base[2], uint32_t bbuf, int nb_local,
    int kc, int lr, int ahalf, int bhalf, int brow, int b6half, int b6row,
    float acc[2][7][4])
{
    constexpr int PAIRS = NT / 2;
    constexpr int REM = NT & 1;
    uint32_t b_base[3], b_base6 = 0;
#pragma unroll
    for (int p = 0; p < PAIRS; p++)
        b_base[p] = bbuf + (uint32_t)(nb_local + p * 16 + brow) * BKB;
    if (REM)
        b_base6 = bbuf + (uint32_t)(nb_local + PAIRS * 16 + b6row) * BKB;

#pragma unroll
    for (int kk = 0; kk < 8; kk++) {
        const int ks = kc * 8 + kk;
        const uint32_t aoff = (uint32_t)((((ks << 1) + ahalf) ^ lr) << 4);
        const uint32_t boff = (uint32_t)((((kk << 1) + bhalf) ^ lr) << 4);

        uint32_t bf[7][2];
#pragma unroll
        for (int p = 0; p < PAIRS; p++)
            ldsm4(bf[2*p][0], bf[2*p][1], bf[2*p+1][0], bf[2*p+1][1], b_base[p] + boff);
        if (REM) {
            const uint32_t b6off = (uint32_t)((((kk << 1) + b6half) ^ b6row) << 4);
            ldsm2(bf[NT-1][0], bf[NT-1][1], b_base6 + b6off);
        }

        uint32_t af[MT][4];
#pragma unroll
        for (int mt = 0; mt < MT; mt++)
            ldsm4(af[mt][0], af[mt][1], af[mt][2], af[mt][3], a_base[mt] + aoff);

#pragma unroll
        for (int mt = 0; mt < MT; mt++)
#pragma unroll
            for (int nt = 0; nt < NT; nt++)
                mma16816(acc[mt][nt], af[mt][0], af[mt][1], af[mt][2], af[mt][3],
                         bf[nt][0], bf[nt][1]);
    }
}

// ---------------- Kernel 2: per-(m,c) GEMM + rowmax + top-6 ----------------
// 14 compute warps = 7 M-slots (6x32 + 1x16 rows = 208 exact) x 2 N-slots.
// Warps 14-15 = dedicated B loaders. N padded to 200 (chunk0 112, chunk1 88).
// PROLOGUE ISSUED BY COMPUTE THREADS ONLY (448): each issuing thread later
// CP_WAITs its own groups and joins BAR_SYNC(5,NCW), making all prologue
// bytes visible before first read (this was the R10 correctness bug).
// Loaders fill B_{it+2} after a buffer-free bar.sync, then signal via
// cp.async.mbarrier.arrive; compute waits mbarrier parity. No mid-loop
// __syncthreads.
__global__ __launch_bounds__(NTHR, 1) void protonet_kernel(
    const float* __restrict__ scale_cls, const float* __restrict__ bias,
    float* __restrict__ out)
{
    extern __shared__ char smem[];
    const uint32_t sb = smem_u32(smem);
    const int tid = threadIdx.x, wid = tid >> 5, lane = tid & 31;
    const int c = blockIdx.x, m = blockIdx.y;
    const int mslot = wid >> 1;          // 0..6 compute, 7 = loader
    const int nslot = wid & 1;
    const int MT = (mslot < 6) ? 2 : ((mslot == 6) ? 1 : 0);

    const char* qg = (const char*)(g_QN + (size_t)m * PP * DD);
    const char* sg = (const char*)(g_SN + (size_t)c * PP * DD);

    if (tid == 0) {
        MBAR_INIT(sb + SM_MB, 64);
        MBAR_INIT(sb + SM_MB + 8, 64);
    }

    // ---- prologue (COMPUTE THREADS ONLY): G0={A_k0,B_it0}, G1={A_k1,B_it1},
    //      G2={A_k2} ----
    if (tid < NCW) {
#pragma unroll 1
        for (int kc = 0; kc < NKC; kc++) {
            for (int i = tid; i < AP * 16; i += NCW) {
                int r = i >> 4, ch = kc * 16 + (i & 15);
                int rc = r < PP ? r : PP - 1;
                cp16(sb + (uint32_t)r * ROWB + (uint32_t)((ch ^ (r & 7)) << 4),
                     qg + (size_t)rc * ROWB + (ch << 4));
            }
            if (kc < 2) {   // B for iteration kc (n-chunk 0, k-chunk kc) -> buf kc
                uint32_t bb = sb + (kc ? SM_B1 : SM_B0);
                for (int i = tid; i < BN0 * 16; i += NCW) {
                    int r = i >> 4, ch = i & 15;
                    int q = r < PP ? r : PP - 1;
                    cp16(bb + (uint32_t)r * BKB + (uint32_t)((ch ^ (r & 7)) << 4),
                         sg + (size_t)q * ROWB + kc * 256 + (ch << 4));
                }
            }
            CP_COMMIT();
        }
    }
    __syncthreads();   // mbar init visible to loaders before any arrive

    const float NEG = __int_as_float(0xff800000);
    float rmax[4];
#pragma unroll
    for (int i = 0; i < 4; i++) rmax[i] = NEG;

    if (wid < 14) {
        // ================= compute warps =================
        const int lm = lane >> 3, lr = lane & 7;
        const int arow  = ((lm & 1) << 3) + lr;
        const int ahalf = lm >> 1;
        const int brow  = ((lm >> 1) << 3) + lr;
        const int bhalf = lm & 1;
        const int b6row = lane & 7;
        const int b6half = (lane >> 3) & 1;

        uint32_t a_base[2];
#pragma unroll
        for (int mt = 0; mt < 2; mt++) {
            int rb = mslot * 32 + mt * 16;
            if (rb > 192) rb = 192;
            a_base[mt] = sb + (uint32_t)(rb + arow) * ROWB;
        }

        float acc[2][7][4];

#pragma unroll 1
        for (int it = 0; it < NIT; it++) {
            const int nc = it / NKC, kc = it - nc * NKC;
            if (kc == 0) {
#pragma unroll
                for (int mt = 0; mt < 2; mt++)
#pragma unroll
                    for (int nt = 0; nt < 7; nt++)
#pragma unroll
                        for (int j = 0; j < 4; j++) acc[mt][nt][j] = 0.f;
            }

            // data-ready (prologue groups are all compute-issued; each thread
            // waits its own, then compute-wide barrier => visibility)
            if (it == 0)      { CP_WAIT(2); BAR_SYNC(5, NCW); }
            else if (it == 1) { CP_WAIT(1); BAR_SYNC(5, NCW); }
            else if (it == 2) { CP_WAIT(0); BAR_SYNC(5, NCW);
                                MBAR_WAIT(sb + SM_MB, 0); }
            else              { MBAR_WAIT(sb + SM_MB + (it & 1) * 8,
                                          ((it - 2) >> 1) & 1); }

            const uint32_t bbuf = sb + ((it & 1) ? SM_B1 : SM_B0);
            const int nb_local = nc ? nslot * 48 : nslot * 56;

            if (nc == 0) {
                if (MT == 2) do_ksteps<2,7>(a_base, bbuf, nb_local, kc, lr, ahalf, bhalf, brow, b6half, b6row, acc);
                else         do_ksteps<1,7>(a_base, bbuf, nb_local, kc, lr, ahalf, bhalf, brow, b6half, b6row, acc);
            } else if (nslot == 0) {
                if (MT == 2) do_ksteps<2,6>(a_base, bbuf, nb_local, kc, lr, ahalf, bhalf, brow, b6half, b6row, acc);
                else         do_ksteps<1,6>(a_base, bbuf, nb_local, kc, lr, ahalf, bhalf, brow, b6half, b6row, acc);
            } else {
                if (MT == 2) do_ksteps<2,5>(a_base, bbuf, nb_local, kc, lr, ahalf, bhalf, brow, b6half, b6row, acc);
                else         do_ksteps<1,5>(a_base, bbuf, nb_local, kc, lr, ahalf, bhalf, brow, b6half, b6row, acc);
            }

            if (kc == NKC - 1 && MT) {   // fold row-max (mask padded cols)
                const int ntiles = nc ? (nslot ? 5 : 6) : 7;
                const int cb = nc * BN0 + nb_local + ((lane & 3) << 1);
#pragma unroll
                for (int mt = 0; mt < 2; mt++) {
                    if (mt >= MT) break;
#pragma unroll
                    for (int nt = 0; nt < 7; nt++) {
                        if (nt >= ntiles) break;
#pragma unroll
                        for (int j = 0; j < 4; j++) {
                            int col = cb + nt * 8 + (j & 1);
                            if (col < PP)
                                rmax[mt * 2 + (j >> 1)] =
                                    fmaxf(rmax[mt * 2 + (j >> 1)], acc[mt][nt][j]);
                        }
                    }
                }
            }

            if (it + 2 < NIT)   // buffer (it&1) free for refill (non-blocking)
                BAR_ARRIVE(3 + (it & 1), NTHR);
        }
    } else {
        // ================= loader warps (14,15) =================
        const int lt = tid - NCW;   // 0..63
#pragma unroll 1
        for (int nit = 2; nit < NIT; nit++) {
            const int bsel = nit & 1;
            BAR_SYNC(3 + bsel, NTHR);   // wait: all compute read buf at nit-2
            const int nnc = nit / NKC, nkc = nit - nnc * NKC;
            const int width = nnc ? BN1 : BN0;
            const uint32_t bb = sb + (bsel ? SM_B1 : SM_B0);
            for (int i = lt; i < width * 16; i += 64) {
                int r = i >> 4, ch = i & 15;
                int q = nnc * BN0 + r;
                if (q > PP - 1) q = PP - 1;
                cp16(bb + (uint32_t)r * BKB + (uint32_t)((ch ^ (r & 7)) << 4),
                     sg + (size_t)q * ROWB + nkc * 256 + (ch << 4));
            }
            CPASYNC_MBAR_ARRIVE(sb + SM_MB + bsel * 8);
        }
    }

    // reduce across the 4 lanes of each row-quad (disjoint cols)
#pragma unroll
    for (int o = 1; o <= 2; o <<= 1)
#pragma unroll
        for (int i = 0; i < 4; i++)
            rmax[i] = fmaxf(rmax[i], __shfl_xor_sync(0xffffffffu, rmax[i], o));

    float* rm = (float*)(smem + SM_RM);
    if (MT && nslot == 0 && (lane & 3) == 0) {
#pragma unroll
        for (int mt = 0; mt < 2; mt++) {
            if (mt >= MT) break;
#pragma unroll
            for (int h = 0; h < 2; h++) {
                int row = mslot * 32 + mt * 16 + h * 8 + (lane >> 2);
                if (row < PP) rm[row] = rmax[mt * 2 + h];
            }
        }
    }
    __syncthreads();
    if (MT && nslot == 1 && (lane & 3) == 0) {
#pragma unroll
        for (int mt = 0; mt < 2; mt++) {
            if (mt >= MT) break;
#pragma unroll
            for (int h = 0; h < 2; h++) {
                int row = mslot * 32 + mt * 16 + h * 8 + (lane >> 2);
                if (row < PP) rm[row] = fmaxf(rm[row], rmax[mt * 2 + h]);
            }
        }
    }
    __syncthreads();

    // top-6 over 196 row-max values (warp 0)
    if (wid == 0) {
        float v[7];
#pragma unroll
        for (int k = 0; k < 7; k++) {
            int idx = lane + 32 * k;
            v[k] = (idx < PP) ? rm[idx] : NEG;
        }
        float sum = 0.f;
#pragma unroll
        for (int itk = 0; itk < 6; itk++) {
            float best = v[0]; int bslot = 0;
#pragma unroll
            for (int k = 1; k < 7; k++)
                if (v[k] > best) { best = v[k]; bslot = k; }
            int bid = lane;
#pragma unroll
            for (int o = 16; o; o >>= 1) {
                float ov = __shfl_xor_sync(0xffffffffu, best, o);
                int  oid = __shfl_xor_sync(0xffffffffu, bid, o);
                int  osl = __shfl_xor_sync(0xffffffffu, bslot, o);
                if (ov > best || (ov == best && oid < bid)) {
                    best = ov; bid = oid; bslot = osl;
                }
            }
            sum += best;
            if (lane == bid) v[bslot] = NEG;
        }
        if (lane == 0)
            out[m * NCLS + c] = scale_cls[0] * (sum + bias[0]);
    }
}

// ---------------- launch ----------------
extern "C" void kernel_launch(void* const* d_in, const int* in_sizes, int n_in,
                              void* d_out, int out_size)
{
    (void)in_sizes; (void)n_in; (void)out_size;
    const float* support   = (const float*)d_in[0];
    const float* query     = (const float*)d_in[1];
    const float* scale_cls = (const float*)d_in[2];
    const float* bias      = (const float*)d_in[3];
    float* out = (float*)d_out;

    int nrows = NROWS_Q + NROWS_S;
    norm_kernel<<<(nrows + 3) / 4, 128>>>(support, query);

    cudaFuncSetAttribute(protonet_kernel,
                         cudaFuncAttributeMaxDynamicSharedMemorySize, SMEM_BYTES);
    // grid.x = class (Sn tiny, L2-resident); grid.y = m so a wave shares Qn
    // rows across the 5 classes via L2.
    protonet_kernel<<<dim3(NCLS, MIMG), NTHR, SMEM_BYTES>>>(scale_cls, bias, out);
}